// round 10
// baseline (speedup 1.0000x reference)
#include <cuda_runtime.h>
#include <cuda_bf16.h>
#include <cstdint>

#define B_   16
#define T_   1024
#define DIN  4608
#define DRED 128
#define H_   32
#define G3   96          // 3*H
#define TAU  12
#define QPV  1e4f

// ---------------- scratch (no cudaMalloc allowed) ----------------
__device__ __nv_bfloat16 g_wc_hi[G3 * DIN];  // folded weight, bf16 hi part
__device__ __nv_bfloat16 g_wc_lo[G3 * DIN];  // folded weight, bf16 lo part
__device__ float g_bc[G3];                   // folded bias b_ih + w_ih@b_dr
__device__ float g_gi[B_ * T_ * G3];         // input-gate preactivations
__device__ float g_hs[B_ * T_ * H_];         // GRU hidden states

__device__ __forceinline__ float sigmoid_fast(float x) {
    return __fdividef(1.f, 1.f + __expf(-x));
}
__device__ __forceinline__ float tanh_fast(float x) {
    return 2.f * __fdividef(1.f, 1.f + __expf(-2.f * x)) - 1.f;
}

// ---------------- prep: fold the two linear layers ----------------
__global__ void prep_bc(const float* __restrict__ w_ih,
                        const float* __restrict__ b_dr,
                        const float* __restrict__ b_ih) {
    int o = threadIdx.x;              // 96 threads
    float acc = b_ih[o];
    #pragma unroll 8
    for (int r = 0; r < DRED; r++) acc = fmaf(w_ih[o * DRED + r], b_dr[r], acc);
    g_bc[o] = acc;
}

// w_c[o][d] = sum_r w_ih[o][r] * w_dr[r][d]; split into bf16 hi/lo
__global__ void __launch_bounds__(128) prep_wc(const float* __restrict__ w_ih,
                                               const float* __restrict__ w_dr) {
    int tid = threadIdx.x;
    int d = blockIdx.x * 128 + tid;   // 36 blocks * 128 = 4608 columns
    float acc[G3];
    #pragma unroll
    for (int o = 0; o < G3; o++) acc[o] = 0.f;
    for (int r = 0; r < DRED; r++) {
        float a = w_dr[(size_t)r * DIN + d];
        #pragma unroll
        for (int o = 0; o < G3; o++)
            acc[o] = fmaf(__ldg(&w_ih[o * DRED + r]), a, acc[o]);
    }
    #pragma unroll
    for (int o = 0; o < G3; o++) {
        float v = acc[o];
        __nv_bfloat16 hi = __float2bfloat16(v);
        __nv_bfloat16 lo = __float2bfloat16(v - __bfloat162float(hi));
        g_wc_hi[(size_t)o * DIN + d] = hi;
        g_wc_lo[(size_t)o * DIN + d] = lo;
    }
}

// ---------------- big GEMM: gi = x @ w_c.T + b_c  (bf16x3 HMMA) ----------------
// M=16384, N=96, K=4608.  Block tile 128x96xBK32, 8 warps (4x2), warp 32x48.
#define GBM 128
#define GBN 96
#define GBK 32
#define APAD 40   // bf16 elems per smem row (80 B, conflict-spread)

__device__ __forceinline__ void mma_bf16(float c[4], const uint32_t a[4],
                                         uint32_t b0, uint32_t b1) {
    asm volatile(
        "mma.sync.aligned.m16n8k16.row.col.f32.bf16.bf16.f32 "
        "{%0,%1,%2,%3}, {%4,%5,%6,%7}, {%8,%9}, {%0,%1,%2,%3};\n"
        : "+f"(c[0]), "+f"(c[1]), "+f"(c[2]), "+f"(c[3])
        : "r"(a[0]), "r"(a[1]), "r"(a[2]), "r"(a[3]), "r"(b0), "r"(b1));
}

__global__ void __launch_bounds__(256) gemm_gi(const float* __restrict__ x) {
    __shared__ __nv_bfloat16 As_hi[GBM][APAD], As_lo[GBM][APAD];  // 20 KB
    __shared__ __nv_bfloat16 Bs_hi[GBN][APAD], Bs_lo[GBN][APAD];  // 15 KB
    int tid = threadIdx.x;
    int wid = tid >> 5, lane = tid & 31;
    int wm = wid & 3, wn = wid >> 2;          // 4 x 2 warp grid
    int g = lane >> 2, tq = lane & 3;         // fragment row-group / quad
    int mBase = blockIdx.x * GBM;

    float c[2][6][4];
    #pragma unroll
    for (int mt = 0; mt < 2; mt++)
        #pragma unroll
        for (int nt = 0; nt < 6; nt++)
            #pragma unroll
            for (int i = 0; i < 4; i++) c[mt][nt][i] = 0.f;

    for (int kb = 0; kb < DIN; kb += GBK) {
        // --- A tile: 128x32 fp32 -> bf16 hi/lo in smem ---
        #pragma unroll
        for (int i = 0; i < 4; i++) {
            int idx = tid + i * 256;           // 0..1023
            int row = idx >> 3, kq = idx & 7;  // cols 4kq..4kq+3
            float4 v = *reinterpret_cast<const float4*>(
                x + (size_t)(mBase + row) * DIN + kb + 4 * kq);
            __nv_bfloat16 h0 = __float2bfloat16(v.x);
            __nv_bfloat16 h1 = __float2bfloat16(v.y);
            __nv_bfloat16 h2 = __float2bfloat16(v.z);
            __nv_bfloat16 h3 = __float2bfloat16(v.w);
            __nv_bfloat16 l0 = __float2bfloat16(v.x - __bfloat162float(h0));
            __nv_bfloat16 l1 = __float2bfloat16(v.y - __bfloat162float(h1));
            __nv_bfloat16 l2 = __float2bfloat16(v.z - __bfloat162float(h2));
            __nv_bfloat16 l3 = __float2bfloat16(v.w - __bfloat162float(h3));
            *reinterpret_cast<__nv_bfloat162*>(&As_hi[row][4 * kq])     = {h0, h1};
            *reinterpret_cast<__nv_bfloat162*>(&As_hi[row][4 * kq + 2]) = {h2, h3};
            *reinterpret_cast<__nv_bfloat162*>(&As_lo[row][4 * kq])     = {l0, l1};
            *reinterpret_cast<__nv_bfloat162*>(&As_lo[row][4 * kq + 2]) = {l2, l3};
        }
        // --- B tile: 96x32 bf16 hi/lo ---
        #pragma unroll
        for (int i = 0; i < 6; i++) {
            int idx = tid + i * 256;            // 0..1535
            int n = idx >> 4, kq = idx & 15;    // bf16 cols 2kq..2kq+1
            *reinterpret_cast<__nv_bfloat162*>(&Bs_hi[n][2 * kq]) =
                *reinterpret_cast<const __nv_bfloat162*>(&g_wc_hi[(size_t)n * DIN + kb + 2 * kq]);
            *reinterpret_cast<__nv_bfloat162*>(&Bs_lo[n][2 * kq]) =
                *reinterpret_cast<const __nv_bfloat162*>(&g_wc_lo[(size_t)n * DIN + kb + 2 * kq]);
        }
        __syncthreads();

        #pragma unroll
        for (int ks = 0; ks < 2; ks++) {
            uint32_t ah[2][4], al[2][4];
            #pragma unroll
            for (int mt = 0; mt < 2; mt++) {
                int r = wm * 32 + mt * 16 + g;
                int cbase = ks * 16 + 2 * tq;
                ah[mt][0] = *reinterpret_cast<const uint32_t*>(&As_hi[r][cbase]);
                ah[mt][1] = *reinterpret_cast<const uint32_t*>(&As_hi[r + 8][cbase]);
                ah[mt][2] = *reinterpret_cast<const uint32_t*>(&As_hi[r][cbase + 8]);
                ah[mt][3] = *reinterpret_cast<const uint32_t*>(&As_hi[r + 8][cbase + 8]);
                al[mt][0] = *reinterpret_cast<const uint32_t*>(&As_lo[r][cbase]);
                al[mt][1] = *reinterpret_cast<const uint32_t*>(&As_lo[r + 8][cbase]);
                al[mt][2] = *reinterpret_cast<const uint32_t*>(&As_lo[r][cbase + 8]);
                al[mt][3] = *reinterpret_cast<const uint32_t*>(&As_lo[r + 8][cbase + 8]);
            }
            #pragma unroll
            for (int nt = 0; nt < 6; nt++) {
                int nr = wn * 48 + nt * 8 + g;
                int cbase = ks * 16 + 2 * tq;
                uint32_t bh0 = *reinterpret_cast<const uint32_t*>(&Bs_hi[nr][cbase]);
                uint32_t bh1 = *reinterpret_cast<const uint32_t*>(&Bs_hi[nr][cbase + 8]);
                uint32_t bl0 = *reinterpret_cast<const uint32_t*>(&Bs_lo[nr][cbase]);
                uint32_t bl1 = *reinterpret_cast<const uint32_t*>(&Bs_lo[nr][cbase + 8]);
                #pragma unroll
                for (int mt = 0; mt < 2; mt++) {
                    mma_bf16(c[mt][nt], ah[mt], bh0, bh1);   // hi*hi
                    mma_bf16(c[mt][nt], ah[mt], bl0, bl1);   // hi*lo
                    mma_bf16(c[mt][nt], al[mt], bh0, bh1);   // lo*hi
                }
            }
        }
        __syncthreads();
    }

    // epilogue: + bias, store
    #pragma unroll
    for (int mt = 0; mt < 2; mt++) {
        int m0r = mBase + wm * 32 + mt * 16 + g;
        #pragma unroll
        for (int nt = 0; nt < 6; nt++) {
            int col = wn * 48 + nt * 8 + 2 * tq;
            float b0 = g_bc[col], b1 = g_bc[col + 1];
            float2 v0 = {c[mt][nt][0] + b0, c[mt][nt][1] + b1};
            float2 v1 = {c[mt][nt][2] + b0, c[mt][nt][3] + b1};
            *reinterpret_cast<float2*>(&g_gi[(size_t)m0r * G3 + col]) = v0;
            *reinterpret_cast<float2*>(&g_gi[(size_t)(m0r + 8) * G3 + col]) = v1;
        }
    }
}

// ---------------- GRU: 4 warps per batch, K-split matvec ----------------
// Warp w computes partial dots over h[8w..8w+7] (24 FMA/lane, own SMSP).
// One __syncthreads per step; every warp redundantly reduces + computes
// activations, so each warp holds the full h vector in its lanes and the
// next step's K-slice comes from an intra-warp shfl (no 2nd barrier).
__global__ void __launch_bounds__(128) gru_kernel(const float* __restrict__ w_hh,
                                                  const float* __restrict__ b_hh) {
    __shared__ float sp[2][4][3][32];   // [parity][warp][gate][elem] = 3 KB
    int b = blockIdx.x;
    int tid = threadIdx.x, w = tid >> 5, lane = tid & 31;

    // per-lane weights: rows (lane, 32+lane, 64+lane), K-slice 8w..8w+7
    float wr[8], wz[8], wn[8];
    {
        const float4* r0 = reinterpret_cast<const float4*>(&w_hh[lane * 32 + 8 * w]);
        const float4* z0 = reinterpret_cast<const float4*>(&w_hh[(32 + lane) * 32 + 8 * w]);
        const float4* n0 = reinterpret_cast<const float4*>(&w_hh[(64 + lane) * 32 + 8 * w]);
        float4 a = r0[0], bb = r0[1];
        wr[0] = a.x; wr[1] = a.y; wr[2] = a.z; wr[3] = a.w;
        wr[4] = bb.x; wr[5] = bb.y; wr[6] = bb.z; wr[7] = bb.w;
        a = z0[0]; bb = z0[1];
        wz[0] = a.x; wz[1] = a.y; wz[2] = a.z; wz[3] = a.w;
        wz[4] = bb.x; wz[5] = bb.y; wz[6] = bb.z; wz[7] = bb.w;
        a = n0[0]; bb = n0[1];
        wn[0] = a.x; wn[1] = a.y; wn[2] = a.z; wn[3] = a.w;
        wn[4] = bb.x; wn[5] = bb.y; wn[6] = bb.z; wn[7] = bb.w;
    }
    float bhr = b_hh[lane], bhz = b_hh[32 + lane], bhn = b_hh[64 + lane];
    const float* gib = g_gi + (size_t)b * T_ * G3;
    float* hsb = g_hs + (size_t)b * T_ * H_;

    // prefetch gi depth 2 (all warps load the same -> L1 broadcast)
    float grA = gib[lane],      gzA = gib[32 + lane],      gnA = gib[64 + lane];
    float grB = gib[G3 + lane], gzB = gib[G3 + 32 + lane], gnB = gib[G3 + 64 + lane];

    float h = 0.f;   // lane's own h element (replicated across warps)

    for (int t = 0; t < T_; t++) {
        int p = t & 1;
        int tp = (t + 2 < T_) ? (t + 2) : (T_ - 1);
        const float* pf = gib + (size_t)tp * G3;
        float grC = pf[lane], gzC = pf[32 + lane], gnC = pf[64 + lane];

        // this warp's 8 h values via intra-warp broadcast
        float hj[8];
        #pragma unroll
        for (int j = 0; j < 8; j++)
            hj[j] = __shfl_sync(0xffffffffu, h, 8 * w + j);

        // partial dots (24 FMA, 3 chains of 8)
        float pr = 0.f, pz = 0.f, pn = 0.f;
        #pragma unroll
        for (int j = 0; j < 8; j++) {
            pr = fmaf(wr[j], hj[j], pr);
            pz = fmaf(wz[j], hj[j], pz);
            pn = fmaf(wn[j], hj[j], pn);
        }
        sp[p][w][0][lane] = pr;
        sp[p][w][1][lane] = pz;
        sp[p][w][2][lane] = pn;
        __syncthreads();

        // redundant cross-warp reduction (12 conflict-free LDS + 9 FADD)
        float ar = (sp[p][0][0][lane] + sp[p][1][0][lane]) +
                   (sp[p][2][0][lane] + sp[p][3][0][lane]);
        float az = (sp[p][0][1][lane] + sp[p][1][1][lane]) +
                   (sp[p][2][1][lane] + sp[p][3][1][lane]);
        float an = (sp[p][0][2][lane] + sp[p][1][2][lane]) +
                   (sp[p][2][2][lane] + sp[p][3][2][lane]);

        float r = sigmoid_fast(grA + ar + bhr);
        float z = sigmoid_fast(gzA + az + bhz);
        float n = tanh_fast(gnA + r * (an + bhn));
        float hn = n + z * (h - n);            // (1-z)*n + z*h
        if (w == 0) hsb[t * H_ + lane] = hn;
        h = hn;
        grA = grB; gzA = gzB; gnA = gnB;
        grB = grC; gzB = gzC; gnB = gnC;
    }
}

// ---------------- post: q, windows, masked mean, output head ----------------
__global__ void __launch_bounds__(128) post_kernel(
        const int* __restrict__ x_len,
        const float* __restrict__ w_reg, const float* __restrict__ b_reg,
        const float* __restrict__ wn1, const float* __restrict__ bn1,
        const float* __restrict__ wn2, const float* __restrict__ bn2,
        const float* __restrict__ wlm, const float* __restrict__ blm,
        float* __restrict__ out, int out_size) {
    __shared__ float sq[T_];
    __shared__ float red[128];
    __shared__ float swr[32];
    int b = blockIdx.x, tid = threadIdx.x;
    int len = x_len[b];
    if (tid < 32) swr[tid] = w_reg[tid];
    __syncthreads();
    float br = b_reg[0];
    const float* hsb = g_hs + (size_t)b * T_ * H_;

    for (int t = tid; t < T_; t += 128) {
        const float* hp = hsb + t * H_;
        float acc = 0.f;
        #pragma unroll
        for (int j = 0; j < 32; j++) acc = fmaf(hp[j], swr[j], acc);
        sq[t] = acc + br;
    }
    __syncthreads();

    float sum = 0.f;
    for (int t = tid; t < T_; t += 128) {
        if (t < len) {
            float l = sq[t];
            #pragma unroll
            for (int k = 1; k < TAU; k++) {
                int i = t - k;
                if (i >= 0) l = fminf(l, sq[i]);
            }
            float num = 0.f, den = 0.f;
            #pragma unroll
            for (int k = 0; k < TAU; k++) {
                int i = t + k;
                float v = (i < len) ? sq[i] : QPV;
                float e = __expf(-v);
                num = fmaf(v, e, num);
                den += e;
            }
            float m = num / den;
            sum += 0.5f * m + 0.5f * l;
        }
    }
    red[tid] = sum;
    __syncthreads();
    for (int s = 64; s > 0; s >>= 1) {
        if (tid < s) red[tid] += red[tid + s];
        __syncthreads();
    }
    if (tid == 0) {
        float rel      = red[0] / (float)len;
        float relative = 1.f / (1.f + expf(-rel));
        float mapped   = wn2[0] * (1.f / (1.f + expf(-(relative * wn1[0] + bn1[0])))) + bn2[0];
        float aligned  = mapped * wlm[0] + blm[0];
        if (out_size >= 3 * B_) {
            out[b] = relative; out[B_ + b] = mapped; out[2 * B_ + b] = aligned;
        } else {
            out[b] = aligned;
        }
    }
}

// ---------------- launch ----------------
extern "C" void kernel_launch(void* const* d_in, const int* in_sizes, int n_in,
                              void* d_out, int out_size) {
    const float* x     = (const float*)d_in[0];
    const int*   xlen  = (const int*)  d_in[1];
    const float* w_dr  = (const float*)d_in[2];
    const float* b_dr  = (const float*)d_in[3];
    const float* w_ih  = (const float*)d_in[4];
    const float* w_hh  = (const float*)d_in[5];
    const float* b_ih  = (const float*)d_in[6];
    const float* b_hh  = (const float*)d_in[7];
    const float* w_reg = (const float*)d_in[8];
    const float* b_reg = (const float*)d_in[9];
    const float* wn1   = (const float*)d_in[10];
    const float* bn1   = (const float*)d_in[11];
    const float* wn2   = (const float*)d_in[12];
    const float* bn2   = (const float*)d_in[13];
    const float* wlm   = (const float*)d_in[14];
    const float* blm   = (const float*)d_in[15];

    prep_wc<<<DIN / 128, 128>>>(w_ih, w_dr);
    prep_bc<<<1, G3>>>(w_ih, b_dr, b_ih);
    gemm_gi<<<(B_ * T_) / GBM, 256>>>(x);
    gru_kernel<<<B_, 128>>>(w_hh, b_hh);
    post_kernel<<<B_, 128>>>(xlen, w_reg, b_reg, wn1, bn1, wn2, bn2, wlm, blm,
                             (float*)d_out, out_size);
}